// round 14
// baseline (speedup 1.0000x reference)
#include <cuda_runtime.h>
#include <cstdint>

// Shapes (fixed)
#define B_    64
#define S_    16
#define J_    256
#define QDIM_ 512
#define IDIM_ 512
#define HDIM_ 256
#define BS_   (B_ * S_)    // 1024
#define CHK_  8            // rows per chunk (1 row per warp)
#define NCHK_ (J_ / CHK_)  // 32 chunks

// Scratch (__device__ globals; 16B-aligned: accessed as float4/float2)
__device__ __align__(16) float g_Q[B_ * HDIM_];        // Wq q               [64, 256]
__device__ __align__(16) float g_qt[B_ * IDIM_];       // scale*Wk^T(Wq q)   [64, 512]
__device__ __align__(16) float g_pooled[BS_ * IDIM_];  // pooled inputs      [1024, 512]
__device__ __align__(16) float g_WvT[IDIM_ * HDIM_];   // Wv^T               [512, 256]
__device__ int g_mask_u8;                              // 1 = u8 bool mask, 0 = int32

// ---------------- cp.async helpers ----------------
__device__ __forceinline__ void cp_async16(unsigned dst_smem, const void* src) {
    asm volatile("cp.async.cg.shared.global [%0], [%1], 16;"
                 :: "r"(dst_smem), "l"(src));
}
__device__ __forceinline__ void cp_commit() {
    asm volatile("cp.async.commit_group;");
}
__device__ __forceinline__ void cp_wait0() {
    asm volatile("cp.async.wait_group 0;");
}
__device__ __forceinline__ void cp_wait1() {
    asm volatile("cp.async.wait_group 1;");
}

// ---------------------------------------------------------------------------
// Kernel 1 (prologue), grid = 192, block = 256:  (identical to R13)
// ---------------------------------------------------------------------------
__global__ __launch_bounds__(256) void prologue_kernel(
    const float*    __restrict__ query,  // [64, 512]
    const float*    __restrict__ Wq,     // [256, 512]
    const float*    __restrict__ Wv,     // [256, 512]
    const unsigned* __restrict__ mask_words)
{
    const int bx  = blockIdx.x;
    const int tid = threadIdx.x;

    if (bx < 128) {
        if (bx == 0) {   // mask dtype detection
            __shared__ int flag;
            if (tid == 0) flag = 0;
            __syncthreads();
            int loc = 0;
            #pragma unroll
            for (int k = 0; k < 4; ++k)
                if (mask_words[tid + 256 * k] > 1u) loc = 1;
            if (loc) flag = 1;
            __syncthreads();
            if (tid == 0) g_mask_u8 = flag;
        }
        __shared__ __align__(16) float tile[32][33];
        const int i0 = (bx & 15) * 32;
        const int h0 = (bx >> 4) * 32;
        const int tx = tid & 31;
        const int ty = tid >> 5;
        #pragma unroll
        for (int r = 0; r < 32; r += 8)
            tile[ty + r][tx] = Wv[(size_t)(h0 + ty + r) * IDIM_ + i0 + tx];
        __syncthreads();
        #pragma unroll
        for (int r = 0; r < 32; r += 8)
            g_WvT[(size_t)(i0 + ty + r) * HDIM_ + h0 + tx] = tile[tx][ty + r];
    } else {
        const int b    = bx - 128;
        const int wid  = tid >> 5;
        const int lane = tid & 31;

        __shared__ __align__(16) float sq[QDIM_];
        sq[tid]       = query[b * QDIM_ + tid];
        sq[tid + 256] = query[b * QDIM_ + tid + 256];
        __syncthreads();

        float4 qr[4];
        {
            const float4* q4 = reinterpret_cast<const float4*>(sq);
            #pragma unroll
            for (int k = 0; k < 4; ++k) qr[k] = q4[lane + 32 * k];
        }

        #pragma unroll 2
        for (int t = 0; t < 32; t += 2) {
            const int h = wid * 32 + t;
            const float4* w0 = reinterpret_cast<const float4*>(Wq + (size_t)h * QDIM_);
            const float4* w1 = reinterpret_cast<const float4*>(Wq + (size_t)(h + 1) * QDIM_);
            float s0 = 0.f, s1 = 0.f;
            #pragma unroll
            for (int k = 0; k < 4; ++k) {
                const float4 a = w0[lane + 32 * k];
                const float4 c = w1[lane + 32 * k];
                s0 = fmaf(a.x, qr[k].x, s0); s0 = fmaf(a.y, qr[k].y, s0);
                s0 = fmaf(a.z, qr[k].z, s0); s0 = fmaf(a.w, qr[k].w, s0);
                s1 = fmaf(c.x, qr[k].x, s1); s1 = fmaf(c.y, qr[k].y, s1);
                s1 = fmaf(c.z, qr[k].z, s1); s1 = fmaf(c.w, qr[k].w, s1);
            }
            #pragma unroll
            for (int off = 16; off > 0; off >>= 1) {
                s0 += __shfl_xor_sync(0xffffffffu, s0, off);
                s1 += __shfl_xor_sync(0xffffffffu, s1, off);
            }
            if (lane == 0) {
                g_Q[b * HDIM_ + h]     = s0;
                g_Q[b * HDIM_ + h + 1] = s1;
            }
        }
    }
}

// ---------------------------------------------------------------------------
// Kernel 1b: qt[b,i] = scale * sum_h Q[b,h] * Wk[h,i]   (identical to R13)
// ---------------------------------------------------------------------------
__global__ __launch_bounds__(256) void qt_kernel(
    const float* __restrict__ Wk)    // [256, 512]
{
    const int b    = blockIdx.x >> 2;
    const int i0   = (blockIdx.x & 3) * 128;
    const int tid  = threadIdx.x;
    const int col  = i0 + (tid & 127);
    const int hh   = tid >> 7;          // 0 or 1

    __shared__ __align__(16) float sQ[HDIM_];
    __shared__ float s_part[256];
    sQ[tid] = g_Q[b * HDIM_ + tid];
    __syncthreads();

    float a[8];
    #pragma unroll
    for (int k = 0; k < 8; ++k) a[k] = 0.f;

    const int hbase = hh * 128;
    #pragma unroll 4
    for (int h = 0; h < 128; h += 8) {
        #pragma unroll
        for (int k = 0; k < 8; ++k)
            a[k] = fmaf(sQ[hbase + h + k],
                        Wk[(size_t)(hbase + h + k) * IDIM_ + col], a[k]);
    }
    s_part[tid] = ((a[0] + a[1]) + (a[2] + a[3])) + ((a[4] + a[5]) + (a[6] + a[7]));
    __syncthreads();

    if (tid < 128) {
        const float scale = 0.0625f;  // 1/sqrt(256)
        g_qt[b * IDIM_ + i0 + tid] = (s_part[tid] + s_part[tid + 128]) * scale;
    }
}

// ---------------------------------------------------------------------------
// Kernel 2: flash softmax-pooling, WARP-AUTONOMOUS pipelines.
// Warp w stages + processes row c*8+w entirely by itself: per-warp cp.async
// groups, __syncwarp only, ZERO block barriers in the main loop. 3-stage
// per-warp buffers. Block barriers only for the final 8-way merge.
// ---------------------------------------------------------------------------
__global__ __launch_bounds__(256, 4) void flash_pool_kernel(
    const float* __restrict__ X,     // [64,16,256,512]
    const void*  __restrict__ mask)  // [64,16,256] u8 or i32
{
    const int bs   = blockIdx.x;
    const int b    = bs >> 4;
    const int tid  = threadIdx.x;
    const int wid  = tid >> 5;
    const int lane = tid & 31;

    // [buf][warp][float4-in-row]; warp w only touches [*][w][*]
    __shared__ __align__(16) float4 s_stage[3][CHK_][128];   // 48 KB
    __shared__ float s_m[8], s_d[8];

    const float4* x4 = reinterpret_cast<const float4*>(X + (size_t)bs * J_ * IDIM_);

    // Mask preload: lane c holds mask bit for row c*8 + wid (this warp's row
    // in chunk c); broadcast per chunk via one shfl.
    int mval;
    {
        const int j = lane * CHK_ + wid;   // 0..255
        if (g_mask_u8)
            mval = ((const uint8_t*)mask)[(size_t)bs * J_ + j];
        else
            mval = ((const int*)mask)[(size_t)bs * J_ + j];
    }

    float4 qv[4];
    {
        const float4* q4 = reinterpret_cast<const float4*>(g_qt + b * IDIM_);
        #pragma unroll
        for (int k = 0; k < 4; ++k) qv[k] = q4[lane + 32 * k];
    }

    const unsigned sbase = (unsigned)__cvta_generic_to_shared(&s_stage[0][0][0]);
    const unsigned BUFB  = (unsigned)(CHK_ * 128 * 16);   // bytes per buffer
    const unsigned rowoff = (unsigned)(wid * 128 + lane) * 16u;

    // Per-warp prologue: stage this warp's rows of chunks 0 and 1
    #pragma unroll
    for (int u = 0; u < 4; ++u)
        cp_async16(sbase + rowoff + (unsigned)(32 * u) * 16u,
                   x4 + (size_t)wid * 128 + lane + 32 * u);
    cp_commit();
    #pragma unroll
    for (int u = 0; u < 4; ++u)
        cp_async16(sbase + BUFB + rowoff + (unsigned)(32 * u) * 16u,
                   x4 + (size_t)(CHK_ + wid) * 128 + lane + 32 * u);
    cp_commit();

    float m = -1e30f, d = 0.f;
    float4 p[4];
    #pragma unroll
    for (int k = 0; k < 4; ++k) p[k] = make_float4(0.f, 0.f, 0.f, 0.f);

    int cur = 0, nxt2 = 2;

    for (int c = 0; c < NCHK_; ++c) {
        if (c == NCHK_ - 1) cp_wait0(); else cp_wait1();   // this warp's row of chunk c
        __syncwarp();

        if (c + 2 < NCHK_) {
            const unsigned sb = sbase + (unsigned)nxt2 * BUFB + rowoff;
            const float4* src = x4 + (size_t)((c + 2) * CHK_ + wid) * 128 + lane;
            #pragma unroll
            for (int u = 0; u < 4; ++u)
                cp_async16(sb + (unsigned)(32 * u) * 16u, src + 32 * u);
            cp_commit();
        }

        // Load this warp's row once; use for both score and p-update.
        const float4* r0 = &s_stage[cur][wid][0];
        float4 xv[4];
        #pragma unroll
        for (int k = 0; k < 4; ++k) xv[k] = r0[lane + 32 * k];

        float s = 0.f;
        #pragma unroll
        for (int k = 0; k < 4; ++k) {
            s = fmaf(xv[k].x, qv[k].x, s);
            s = fmaf(xv[k].y, qv[k].y, s);
            s = fmaf(xv[k].z, qv[k].z, s);
            s = fmaf(xv[k].w, qv[k].w, s);
        }
        #pragma unroll
        for (int off = 16; off > 0; off >>= 1)
            s += __shfl_xor_sync(0xffffffffu, s, off);

        if (__shfl_sync(0xffffffffu, mval, c) != 0) s = -1e30f;

        const float mn = fmaxf(m, s);
        const float f  = __expf(m - mn);
        const float w  = __expf(s - mn);
        m = mn;
        d = fmaf(d, f, w);
        #pragma unroll
        for (int k = 0; k < 4; ++k) {
            p[k].x = fmaf(p[k].x, f, w * xv[k].x);
            p[k].y = fmaf(p[k].y, f, w * xv[k].y);
            p[k].z = fmaf(p[k].z, f, w * xv[k].z);
            p[k].w = fmaf(p[k].w, f, w * xv[k].w);
        }

        cur  = (cur == 2)  ? 0 : cur + 1;
        nxt2 = (nxt2 == 2) ? 0 : nxt2 + 1;
    }

    // ---- merge 8 per-warp states (reuse staging smem: 8 x 512 floats) ----
    __syncthreads();   // all warps finished their pipelines; staging free
    if (lane == 0) { s_m[wid] = m; s_d[wid] = d; }
    {
        float4* mp = reinterpret_cast<float4*>(&s_stage[0][0][0]);
        #pragma unroll
        for (int k = 0; k < 4; ++k) mp[wid * 128 + lane + 32 * k] = p[k];
    }
    __syncthreads();

    float M = -1e30f;
    #pragma unroll
    for (int w = 0; w < 8; ++w) M = fmaxf(M, s_m[w]);
    float coef[8];
    float D = 0.f;
    #pragma unroll
    for (int w = 0; w < 8; ++w) {
        coef[w] = __expf(s_m[w] - M);
        D = fmaf(s_d[w], coef[w], D);
    }
    const float inv = 1.f / D;

    const float2* mp2 = reinterpret_cast<const float2*>(&s_stage[0][0][0]);
    float ox = 0.f, oy = 0.f;
    #pragma unroll
    for (int w = 0; w < 8; ++w) {
        const float2 v = mp2[w * 256 + tid];
        ox = fmaf(v.x, coef[w], ox);
        oy = fmaf(v.y, coef[w], oy);
    }
    reinterpret_cast<float2*>(g_pooled + (size_t)bs * IDIM_)[tid] =
        make_float2(ox * inv, oy * inv);
}

// ---------------------------------------------------------------------------
// Kernel 3: cp.async double-buffered GEMM (identical to R13)
// out[1024,256] = pooled[1024,512] @ WvT[512,256]
// BM=32, BN=64, BK=32; 256 threads, 2x4 register tile; 128 blocks.
// ---------------------------------------------------------------------------
#define BM_ 32
#define BN_ 64
#define BK_ 32
#define SAP_ 36
__global__ __launch_bounds__(256) void epilogue_kernel(float* __restrict__ out)
{
    const int tid = threadIdx.x;
    const int h0  = blockIdx.x * BN_;
    const int m0  = blockIdx.y * BM_;
    const int tx  = tid & 15;
    const int ty  = tid >> 4;

    __shared__ __align__(16) float sA[2][BM_][SAP_];
    __shared__ __align__(16) float sB[2][BK_][BN_];

    float acc[2][4];
    #pragma unroll
    for (int i = 0; i < 2; ++i)
        #pragma unroll
        for (int j = 0; j < 4; ++j) acc[i][j] = 0.f;

    const int ar = tid >> 3;
    const int ac = (tid & 7) * 4;
    const int br = tid >> 4;
    const int bc = (tid & 15) * 4;

    const unsigned sAu = (unsigned)__cvta_generic_to_shared(&sA[0][0][0]);
    const unsigned sBu = (unsigned)__cvta_generic_to_shared(&sB[0][0][0]);
    const unsigned ABUF = (unsigned)(BM_ * SAP_ * 4);
    const unsigned BBUF = (unsigned)(BK_ * BN_ * 4);

    {
        cp_async16(sAu + (unsigned)(ar * SAP_ + ac) * 4u,
                   g_pooled + (size_t)(m0 + ar) * IDIM_ + ac);
        #pragma unroll
        for (int r = 0; r < 2; ++r) {
            const int kk = br + 16 * r;
            cp_async16(sBu + (unsigned)(kk * BN_ + bc) * 4u,
                       g_WvT + (size_t)kk * HDIM_ + h0 + bc);
        }
        cp_commit();
    }

    const int NCH = IDIM_ / BK_;   // 16
    for (int c = 0; c < NCH; ++c) {
        const int cur = c & 1;

        if (c + 1 < NCH) {
            const int k0 = (c + 1) * BK_;
            const unsigned oa = sAu + (unsigned)(cur ^ 1) * ABUF;
            const unsigned ob = sBu + (unsigned)(cur ^ 1) * BBUF;
            cp_async16(oa + (unsigned)(ar * SAP_ + ac) * 4u,
                       g_pooled + (size_t)(m0 + ar) * IDIM_ + k0 + ac);
            #pragma unroll
            for (int r = 0; r < 2; ++r) {
                const int kk = br + 16 * r;
                cp_async16(ob + (unsigned)(kk * BN_ + bc) * 4u,
                           g_WvT + (size_t)(k0 + kk) * HDIM_ + h0 + bc);
            }
            cp_commit();
        }

        if (c + 1 < NCH) cp_wait1(); else cp_wait0();
        __syncthreads();

        #pragma unroll
        for (int kk = 0; kk < BK_; ++kk) {
            const float a0 = sA[cur][ty * 2 + 0][kk];
            const float a1 = sA[cur][ty * 2 + 1][kk];
            const float4 bv = *reinterpret_cast<const float4*>(&sB[cur][kk][tx * 4]);
            acc[0][0] = fmaf(a0, bv.x, acc[0][0]);
            acc[0][1] = fmaf(a0, bv.y, acc[0][1]);
            acc[0][2] = fmaf(a0, bv.z, acc[0][2]);
            acc[0][3] = fmaf(a0, bv.w, acc[0][3]);
            acc[1][0] = fmaf(a1, bv.x, acc[1][0]);
            acc[1][1] = fmaf(a1, bv.y, acc[1][1]);
            acc[1][2] = fmaf(a1, bv.z, acc[1][2]);
            acc[1][3] = fmaf(a1, bv.w, acc[1][3]);
        }
        __syncthreads();
    }

    #pragma unroll
    for (int i = 0; i < 2; ++i) {
        const float4 v = make_float4(acc[i][0], acc[i][1], acc[i][2], acc[i][3]);
        *reinterpret_cast<float4*>(
            out + (size_t)(m0 + ty * 2 + i) * HDIM_ + h0 + tx * 4) = v;
    }
}

// ---------------------------------------------------------------------------
// Launch.  Inputs: query, other_semesters, mask, Wq, Wk, Wv
// ---------------------------------------------------------------------------
extern "C" void kernel_launch(void* const* d_in, const int* in_sizes, int n_in,
                              void* d_out, int out_size)
{
    const float* query = (const float*)d_in[0];
    const float* X     = (const float*)d_in[1];
    const void*  mask  = d_in[2];
    const float* Wq    = (const float*)d_in[3];
    const float* Wk    = (const float*)d_in[4];
    const float* Wv    = (const float*)d_in[5];
    float*       out   = (float*)d_out;

    prologue_kernel<<<192, 256>>>(query, Wq, Wv, (const unsigned*)mask);
    qt_kernel<<<256, 256>>>(Wk);
    flash_pool_kernel<<<BS_, 256>>>(X, mask);
    epilogue_kernel<<<dim3(HDIM_ / BN_, BS_ / BM_), 256>>>(out);
}

// round 15
// speedup vs baseline: 1.0145x; 1.0145x over previous
#include <cuda_runtime.h>
#include <cstdint>

// Shapes (fixed)
#define B_    64
#define S_    16
#define J_    256
#define QDIM_ 512
#define IDIM_ 512
#define HDIM_ 256
#define BS_   (B_ * S_)    // 1024
#define CHK_  8            // rows per staged chunk
#define NCHK_ (J_ / CHK_)  // 32 chunks

// Scratch (__device__ globals; 16B-aligned: accessed as float4/float2)
__device__ __align__(16) float g_Q[B_ * HDIM_];        // Wq q               [64, 256]
__device__ __align__(16) float g_qt[B_ * IDIM_];       // scale*Wk^T(Wq q)   [64, 512]
__device__ __align__(16) float g_pooled[BS_ * IDIM_];  // pooled inputs      [1024, 512]
__device__ __align__(16) float g_WvT[IDIM_ * HDIM_];   // Wv^T               [512, 256]
__device__ int g_mask_u8;                              // 1 = u8 bool mask, 0 = int32

// ---------------- cp.async helpers ----------------
__device__ __forceinline__ void cp_async16(unsigned dst_smem, const void* src) {
    asm volatile("cp.async.cg.shared.global [%0], [%1], 16;"
                 :: "r"(dst_smem), "l"(src));
}
__device__ __forceinline__ void cp_commit() {
    asm volatile("cp.async.commit_group;");
}
__device__ __forceinline__ void cp_wait0() {
    asm volatile("cp.async.wait_group 0;");
}
__device__ __forceinline__ void cp_wait1() {
    asm volatile("cp.async.wait_group 1;");
}

// ---------------------------------------------------------------------------
// Kernel 1 (prologue), grid = 192, block = 256:  (identical to R13)
//   blocks 0..127  : transpose Wv -> g_WvT (block 0 also detects mask dtype)
//   blocks 128..191: Q[b,h] (warp-per-2h, coalesced Wq reads + warp reduce)
// ---------------------------------------------------------------------------
__global__ __launch_bounds__(256) void prologue_kernel(
    const float*    __restrict__ query,  // [64, 512]
    const float*    __restrict__ Wq,     // [256, 512]
    const float*    __restrict__ Wv,     // [256, 512]
    const unsigned* __restrict__ mask_words)
{
    const int bx  = blockIdx.x;
    const int tid = threadIdx.x;

    if (bx < 128) {
        if (bx == 0) {   // mask dtype detection
            __shared__ int flag;
            if (tid == 0) flag = 0;
            __syncthreads();
            int loc = 0;
            #pragma unroll
            for (int k = 0; k < 4; ++k)
                if (mask_words[tid + 256 * k] > 1u) loc = 1;
            if (loc) flag = 1;
            __syncthreads();
            if (tid == 0) g_mask_u8 = flag;
        }
        __shared__ __align__(16) float tile[32][33];
        const int i0 = (bx & 15) * 32;
        const int h0 = (bx >> 4) * 32;
        const int tx = tid & 31;
        const int ty = tid >> 5;
        #pragma unroll
        for (int r = 0; r < 32; r += 8)
            tile[ty + r][tx] = Wv[(size_t)(h0 + ty + r) * IDIM_ + i0 + tx];
        __syncthreads();
        #pragma unroll
        for (int r = 0; r < 32; r += 8)
            g_WvT[(size_t)(i0 + ty + r) * HDIM_ + h0 + tx] = tile[tx][ty + r];
    } else {
        const int b    = bx - 128;
        const int wid  = tid >> 5;
        const int lane = tid & 31;

        __shared__ __align__(16) float sq[QDIM_];
        sq[tid]       = query[b * QDIM_ + tid];
        sq[tid + 256] = query[b * QDIM_ + tid + 256];
        __syncthreads();

        float4 qr[4];
        {
            const float4* q4 = reinterpret_cast<const float4*>(sq);
            #pragma unroll
            for (int k = 0; k < 4; ++k) qr[k] = q4[lane + 32 * k];
        }

        #pragma unroll 2
        for (int t = 0; t < 32; t += 2) {
            const int h = wid * 32 + t;
            const float4* w0 = reinterpret_cast<const float4*>(Wq + (size_t)h * QDIM_);
            const float4* w1 = reinterpret_cast<const float4*>(Wq + (size_t)(h + 1) * QDIM_);
            float s0 = 0.f, s1 = 0.f;
            #pragma unroll
            for (int k = 0; k < 4; ++k) {
                const float4 a = w0[lane + 32 * k];
                const float4 c = w1[lane + 32 * k];
                s0 = fmaf(a.x, qr[k].x, s0); s0 = fmaf(a.y, qr[k].y, s0);
                s0 = fmaf(a.z, qr[k].z, s0); s0 = fmaf(a.w, qr[k].w, s0);
                s1 = fmaf(c.x, qr[k].x, s1); s1 = fmaf(c.y, qr[k].y, s1);
                s1 = fmaf(c.z, qr[k].z, s1); s1 = fmaf(c.w, qr[k].w, s1);
            }
            #pragma unroll
            for (int off = 16; off > 0; off >>= 1) {
                s0 += __shfl_xor_sync(0xffffffffu, s0, off);
                s1 += __shfl_xor_sync(0xffffffffu, s1, off);
            }
            if (lane == 0) {
                g_Q[b * HDIM_ + h]     = s0;
                g_Q[b * HDIM_ + h + 1] = s1;
            }
        }
    }
}

// ---------------------------------------------------------------------------
// Kernel 1b: qt[b,i] = scale * sum_h Q[b,h] * Wk[h,i]   (identical to R13)
// ---------------------------------------------------------------------------
__global__ __launch_bounds__(256) void qt_kernel(
    const float* __restrict__ Wk)    // [256, 512]
{
    const int b    = blockIdx.x >> 2;
    const int i0   = (blockIdx.x & 3) * 128;
    const int tid  = threadIdx.x;
    const int col  = i0 + (tid & 127);
    const int hh   = tid >> 7;          // 0 or 1

    __shared__ __align__(16) float sQ[HDIM_];
    __shared__ float s_part[256];
    sQ[tid] = g_Q[b * HDIM_ + tid];
    __syncthreads();

    float a[8];
    #pragma unroll
    for (int k = 0; k < 8; ++k) a[k] = 0.f;

    const int hbase = hh * 128;
    #pragma unroll 4
    for (int h = 0; h < 128; h += 8) {
        #pragma unroll
        for (int k = 0; k < 8; ++k)
            a[k] = fmaf(sQ[hbase + h + k],
                        Wk[(size_t)(hbase + h + k) * IDIM_ + col], a[k]);
    }
    s_part[tid] = ((a[0] + a[1]) + (a[2] + a[3])) + ((a[4] + a[5]) + (a[6] + a[7]));
    __syncthreads();

    if (tid < 128) {
        const float scale = 0.0625f;  // 1/sqrt(256)
        g_qt[b * IDIM_ + i0 + tid] = (s_part[tid] + s_part[tid + 128]) * scale;
    }
}

// ---------------------------------------------------------------------------
// Kernel 2: flash softmax-pooling, PER-WARP-PRIVATE state (identical to R13:
// best measured). 3-stage block-coop cp.async pipeline, 1 barrier/chunk.
// ---------------------------------------------------------------------------
__global__ __launch_bounds__(256, 4) void flash_pool_kernel(
    const float* __restrict__ X,     // [64,16,256,512]
    const void*  __restrict__ mask)  // [64,16,256] u8 or i32
{
    const int bs   = blockIdx.x;
    const int b    = bs >> 4;
    const int tid  = threadIdx.x;
    const int wid  = tid >> 5;
    const int lane = tid & 31;

    __shared__ __align__(16) float4 s_stage[3][CHK_ * 128];  // 3 x 16 KB (also merge buf)
    __shared__ float s_m[8], s_d[8];

    const float4* x4 = reinterpret_cast<const float4*>(X + (size_t)bs * J_ * IDIM_);

    int mval;
    {
        const int j = lane * CHK_ + wid;   // 0..255
        if (g_mask_u8)
            mval = ((const uint8_t*)mask)[(size_t)bs * J_ + j];
        else
            mval = ((const int*)mask)[(size_t)bs * J_ + j];
    }

    float4 qv[4];
    {
        const float4* q4 = reinterpret_cast<const float4*>(g_qt + b * IDIM_);
        #pragma unroll
        for (int k = 0; k < 4; ++k) qv[k] = q4[lane + 32 * k];
    }

    const unsigned sbase = (unsigned)__cvta_generic_to_shared(&s_stage[0][0]);
    const unsigned BUFB  = (unsigned)(CHK_ * 128 * 16);

    #pragma unroll
    for (int u = 0; u < 4; ++u)
        cp_async16(sbase + (unsigned)(tid + 256 * u) * 16u, x4 + tid + 256 * u);
    cp_commit();
    #pragma unroll
    for (int u = 0; u < 4; ++u)
        cp_async16(sbase + BUFB + (unsigned)(tid + 256 * u) * 16u,
                   x4 + CHK_ * 128 + tid + 256 * u);
    cp_commit();

    float m = -1e30f, d = 0.f;
    float4 p[4];
    #pragma unroll
    for (int k = 0; k < 4; ++k) p[k] = make_float4(0.f, 0.f, 0.f, 0.f);

    int cur = 0, nxt2 = 2;

    for (int c = 0; c < NCHK_; ++c) {
        if (c == NCHK_ - 1) cp_wait0(); else cp_wait1();
        __syncthreads();

        if (c + 2 < NCHK_) {
            const unsigned sb = sbase + (unsigned)nxt2 * BUFB;
            const float4* src = x4 + (size_t)(c + 2) * (CHK_ * 128);
            #pragma unroll
            for (int u = 0; u < 4; ++u)
                cp_async16(sb + (unsigned)(tid + 256 * u) * 16u, src + tid + 256 * u);
            cp_commit();
        }

        const float4* r0 = &s_stage[cur][wid * 128];
        float4 xv[4];
        #pragma unroll
        for (int k = 0; k < 4; ++k) xv[k] = r0[lane + 32 * k];

        float s = 0.f;
        #pragma unroll
        for (int k = 0; k < 4; ++k) {
            s = fmaf(xv[k].x, qv[k].x, s);
            s = fmaf(xv[k].y, qv[k].y, s);
            s = fmaf(xv[k].z, qv[k].z, s);
            s = fmaf(xv[k].w, qv[k].w, s);
        }
        #pragma unroll
        for (int off = 16; off > 0; off >>= 1)
            s += __shfl_xor_sync(0xffffffffu, s, off);

        if (__shfl_sync(0xffffffffu, mval, c) != 0) s = -1e30f;

        const float mn = fmaxf(m, s);
        const float f  = __expf(m - mn);
        const float w  = __expf(s - mn);
        m = mn;
        d = fmaf(d, f, w);
        #pragma unroll
        for (int k = 0; k < 4; ++k) {
            p[k].x = fmaf(p[k].x, f, w * xv[k].x);
            p[k].y = fmaf(p[k].y, f, w * xv[k].y);
            p[k].z = fmaf(p[k].z, f, w * xv[k].z);
            p[k].w = fmaf(p[k].w, f, w * xv[k].w);
        }

        cur  = (cur == 2)  ? 0 : cur + 1;
        nxt2 = (nxt2 == 2) ? 0 : nxt2 + 1;
    }

    __syncthreads();
    if (lane == 0) { s_m[wid] = m; s_d[wid] = d; }
    {
        float4* mp = reinterpret_cast<float4*>(&s_stage[0][0]);
        #pragma unroll
        for (int k = 0; k < 4; ++k) mp[wid * 128 + lane + 32 * k] = p[k];
    }
    __syncthreads();

    float M = -1e30f;
    #pragma unroll
    for (int w = 0; w < 8; ++w) M = fmaxf(M, s_m[w]);
    float coef[8];
    float D = 0.f;
    #pragma unroll
    for (int w = 0; w < 8; ++w) {
        coef[w] = __expf(s_m[w] - M);
        D = fmaf(s_d[w], coef[w], D);
    }
    const float inv = 1.f / D;

    const float2* mp2 = reinterpret_cast<const float2*>(&s_stage[0][0]);
    float ox = 0.f, oy = 0.f;
    #pragma unroll
    for (int w = 0; w < 8; ++w) {
        const float2 v = mp2[w * 256 + tid];
        ox = fmaf(v.x, coef[w], ox);
        oy = fmaf(v.y, coef[w], oy);
    }
    reinterpret_cast<float2*>(g_pooled + (size_t)bs * IDIM_)[tid] =
        make_float2(ox * inv, oy * inv);
}

// ---------------------------------------------------------------------------
// Kernel 3: split-K cp.async GEMM  out[1024,256] = pooled @ WvT
// BM=32, BN=64, BK=32; 512 threads = 2 k-halves x 256; grid 128.
// Each half runs its own double-buffered pipeline over 8 chunks (half the
// serial chain, 4 warps/SMSP); halves combine via smem add at the end.
// ---------------------------------------------------------------------------
#define BM_ 32
#define BN_ 64
#define BK_ 32
#define SAP_ 36
__global__ __launch_bounds__(512) void epilogue_kernel(float* __restrict__ out)
{
    const int tid = threadIdx.x;
    const int kh  = tid >> 8;          // k-half: 0 or 1
    const int t   = tid & 255;
    const int h0  = blockIdx.x * BN_;
    const int m0  = blockIdx.y * BM_;
    const int tx  = t & 15;
    const int ty  = t >> 4;

    __shared__ __align__(16) float sA[2][2][BM_][SAP_];   // [half][buf]
    __shared__ __align__(16) float sB[2][2][BK_][BN_];
    __shared__ __align__(16) float sP[BM_][BN_];          // half-1 partials, 8 KB

    float acc[2][4];
    #pragma unroll
    for (int i = 0; i < 2; ++i)
        #pragma unroll
        for (int j = 0; j < 4; ++j) acc[i][j] = 0.f;

    const int ar = t >> 3;            // 0..31 (m row)
    const int ac = (t & 7) * 4;       // k col (float4)
    const int br = t >> 4;            // 0..15 (k row)
    const int bc = (t & 15) * 4;      // n col (float4)
    const int kbase = kh * 256;       // this half's k-range start

    const unsigned sAu = (unsigned)__cvta_generic_to_shared(&sA[kh][0][0][0]);
    const unsigned sBu = (unsigned)__cvta_generic_to_shared(&sB[kh][0][0][0]);
    const unsigned ABUF = (unsigned)(BM_ * SAP_ * 4);
    const unsigned BBUF = (unsigned)(BK_ * BN_ * 4);

    // Issue chunk 0 of this half
    {
        cp_async16(sAu + (unsigned)(ar * SAP_ + ac) * 4u,
                   g_pooled + (size_t)(m0 + ar) * IDIM_ + kbase + ac);
        #pragma unroll
        for (int r = 0; r < 2; ++r) {
            const int kk = br + 16 * r;
            cp_async16(sBu + (unsigned)(kk * BN_ + bc) * 4u,
                       g_WvT + (size_t)(kbase + kk) * HDIM_ + h0 + bc);
        }
        cp_commit();
    }

    const int NCH = 256 / BK_;   // 8 chunks per half
    for (int c = 0; c < NCH; ++c) {
        const int cur = c & 1;

        if (c + 1 < NCH) {
            const int k0 = kbase + (c + 1) * BK_;
            const unsigned oa = sAu + (unsigned)(cur ^ 1) * ABUF;
            const unsigned ob = sBu + (unsigned)(cur ^ 1) * BBUF;
            cp_async16(oa + (unsigned)(ar * SAP_ + ac) * 4u,
                       g_pooled + (size_t)(m0 + ar) * IDIM_ + k0 + ac);
            #pragma unroll
            for (int r = 0; r < 2; ++r) {
                const int kk = br + 16 * r;
                cp_async16(ob + (unsigned)(kk * BN_ + bc) * 4u,
                           g_WvT + (size_t)(k0 + kk) * HDIM_ + h0 + bc);
            }
            cp_commit();
        }

        if (c + 1 < NCH) cp_wait1(); else cp_wait0();
        // Per-half barrier: named barrier kh with 256 threads
        asm volatile("bar.sync %0, 256;" :: "r"(kh + 1) : "memory");

        #pragma unroll
        for (int kk = 0; kk < BK_; ++kk) {
            const float a0 = sA[kh][cur][ty * 2 + 0][kk];
            const float a1 = sA[kh][cur][ty * 2 + 1][kk];
            const float4 bv = *reinterpret_cast<const float4*>(&sB[kh][cur][kk][tx * 4]);
            acc[0][0] = fmaf(a0, bv.x, acc[0][0]);
            acc[0][1] = fmaf(a0, bv.y, acc[0][1]);
            acc[0][2] = fmaf(a0, bv.z, acc[0][2]);
            acc[0][3] = fmaf(a0, bv.w, acc[0][3]);
            acc[1][0] = fmaf(a1, bv.x, acc[1][0]);
            acc[1][1] = fmaf(a1, bv.y, acc[1][1]);
            acc[1][2] = fmaf(a1, bv.z, acc[1][2]);
            acc[1][3] = fmaf(a1, bv.w, acc[1][3]);
        }
        asm volatile("bar.sync %0, 256;" :: "r"(kh + 1) : "memory");
    }

    // Combine halves: half 1 stashes, half 0 adds and stores
    if (kh == 1) {
        #pragma unroll
        for (int i = 0; i < 2; ++i)
            *reinterpret_cast<float4*>(&sP[ty * 2 + i][tx * 4]) =
                make_float4(acc[i][0], acc[i][1], acc[i][2], acc[i][3]);
    }
    __syncthreads();
    if (kh == 0) {
        #pragma unroll
        for (int i = 0; i < 2; ++i) {
            const float4 o = *reinterpret_cast<const float4*>(&sP[ty * 2 + i][tx * 4]);
            const float4 v = make_float4(acc[i][0] + o.x, acc[i][1] + o.y,
                                         acc[i][2] + o.z, acc[i][3] + o.w);
            *reinterpret_cast<float4*>(
                out + (size_t)(m0 + ty * 2 + i) * HDIM_ + h0 + tx * 4) = v;
        }
    }
}

// ---------------------------------------------------------------------------
// Launch.  Inputs: query, other_semesters, mask, Wq, Wk, Wv
// ---------------------------------------------------------------------------
extern "C" void kernel_launch(void* const* d_in, const int* in_sizes, int n_in,
                              void* d_out, int out_size)
{
    const float* query = (const float*)d_in[0];
    const float* X     = (const float*)d_in[1];
    const void*  mask  = d_in[2];
    const float* Wq    = (const float*)d_in[3];
    const float* Wk    = (const float*)d_in[4];
    const float* Wv    = (const float*)d_in[5];
    float*       out   = (float*)d_out;

    prologue_kernel<<<192, 256>>>(query, Wq, Wv, (const unsigned*)mask);
    qt_kernel<<<256, 256>>>(Wk);
    flash_pool_kernel<<<BS_, 256>>>(X, mask);
    epilogue_kernel<<<dim3(HDIM_ / BN_, BS_ / BM_), 512>>>(out);
}

// round 16
// speedup vs baseline: 1.0166x; 1.0021x over previous
#include <cuda_runtime.h>
#include <cstdint>

// Shapes (fixed)
#define B_    64
#define S_    16
#define J_    256
#define QDIM_ 512
#define IDIM_ 512
#define HDIM_ 256
#define BS_   (B_ * S_)    // 1024
#define CHK_  8            // rows per staged chunk
#define NCHK_ (J_ / CHK_)  // 32 chunks

// Scratch (__device__ globals; 16B-aligned: accessed as float4/float2)
__device__ __align__(16) float g_Q[B_ * HDIM_];        // Wq q               [64, 256]
__device__ __align__(16) float g_qt[B_ * IDIM_];       // scale*Wk^T(Wq q)   [64, 512]
__device__ __align__(16) float g_pooled[BS_ * IDIM_];  // pooled inputs      [1024, 512]
__device__ __align__(16) float g_WvT[IDIM_ * HDIM_];   // Wv^T               [512, 256]
__device__ int g_mask_u8;                              // 1 = u8 bool mask, 0 = int32

// ---------------- cp.async helpers ----------------
__device__ __forceinline__ void cp_async16(unsigned dst_smem, const void* src) {
    asm volatile("cp.async.cg.shared.global [%0], [%1], 16;"
                 :: "r"(dst_smem), "l"(src));
}
__device__ __forceinline__ void cp_commit() {
    asm volatile("cp.async.commit_group;");
}
__device__ __forceinline__ void cp_wait0() {
    asm volatile("cp.async.wait_group 0;");
}
__device__ __forceinline__ void cp_wait1() {
    asm volatile("cp.async.wait_group 1;");
}

// ---------------- f32x2 (FFMA2) helpers ----------------
__device__ __forceinline__ unsigned long long ffma2(
    unsigned long long a, unsigned long long b, unsigned long long c) {
    unsigned long long d;
    asm("fma.rn.f32x2 %0, %1, %2, %3;" : "=l"(d) : "l"(a), "l"(b), "l"(c));
    return d;
}
__device__ __forceinline__ unsigned long long pack2(float x) {
    unsigned long long d;
    asm("mov.b64 %0, {%1, %1};" : "=l"(d) : "f"(x));
    return d;
}
__device__ __forceinline__ void unpack2(float& lo, float& hi, unsigned long long v) {
    asm("mov.b64 {%0, %1}, %2;" : "=f"(lo), "=f"(hi) : "l"(v));
}

// ---------------------------------------------------------------------------
// Kernel 1 (prologue), grid = 192, block = 256:  (identical to R15)
// ---------------------------------------------------------------------------
__global__ __launch_bounds__(256) void prologue_kernel(
    const float*    __restrict__ query,  // [64, 512]
    const float*    __restrict__ Wq,     // [256, 512]
    const float*    __restrict__ Wv,     // [256, 512]
    const unsigned* __restrict__ mask_words)
{
    const int bx  = blockIdx.x;
    const int tid = threadIdx.x;

    if (bx < 128) {
        if (bx == 0) {   // mask dtype detection
            __shared__ int flag;
            if (tid == 0) flag = 0;
            __syncthreads();
            int loc = 0;
            #pragma unroll
            for (int k = 0; k < 4; ++k)
                if (mask_words[tid + 256 * k] > 1u) loc = 1;
            if (loc) flag = 1;
            __syncthreads();
            if (tid == 0) g_mask_u8 = flag;
        }
        __shared__ __align__(16) float tile[32][33];
        const int i0 = (bx & 15) * 32;
        const int h0 = (bx >> 4) * 32;
        const int tx = tid & 31;
        const int ty = tid >> 5;
        #pragma unroll
        for (int r = 0; r < 32; r += 8)
            tile[ty + r][tx] = Wv[(size_t)(h0 + ty + r) * IDIM_ + i0 + tx];
        __syncthreads();
        #pragma unroll
        for (int r = 0; r < 32; r += 8)
            g_WvT[(size_t)(i0 + ty + r) * HDIM_ + h0 + tx] = tile[tx][ty + r];
    } else {
        const int b    = bx - 128;
        const int wid  = tid >> 5;
        const int lane = tid & 31;

        __shared__ __align__(16) float sq[QDIM_];
        sq[tid]       = query[b * QDIM_ + tid];
        sq[tid + 256] = query[b * QDIM_ + tid + 256];
        __syncthreads();

        float4 qr[4];
        {
            const float4* q4 = reinterpret_cast<const float4*>(sq);
            #pragma unroll
            for (int k = 0; k < 4; ++k) qr[k] = q4[lane + 32 * k];
        }

        #pragma unroll 2
        for (int t = 0; t < 32; t += 2) {
            const int h = wid * 32 + t;
            const float4* w0 = reinterpret_cast<const float4*>(Wq + (size_t)h * QDIM_);
            const float4* w1 = reinterpret_cast<const float4*>(Wq + (size_t)(h + 1) * QDIM_);
            float s0 = 0.f, s1 = 0.f;
            #pragma unroll
            for (int k = 0; k < 4; ++k) {
                const float4 a = w0[lane + 32 * k];
                const float4 c = w1[lane + 32 * k];
                s0 = fmaf(a.x, qr[k].x, s0); s0 = fmaf(a.y, qr[k].y, s0);
                s0 = fmaf(a.z, qr[k].z, s0); s0 = fmaf(a.w, qr[k].w, s0);
                s1 = fmaf(c.x, qr[k].x, s1); s1 = fmaf(c.y, qr[k].y, s1);
                s1 = fmaf(c.z, qr[k].z, s1); s1 = fmaf(c.w, qr[k].w, s1);
            }
            #pragma unroll
            for (int off = 16; off > 0; off >>= 1) {
                s0 += __shfl_xor_sync(0xffffffffu, s0, off);
                s1 += __shfl_xor_sync(0xffffffffu, s1, off);
            }
            if (lane == 0) {
                g_Q[b * HDIM_ + h]     = s0;
                g_Q[b * HDIM_ + h + 1] = s1;
            }
        }
    }
}

// ---------------------------------------------------------------------------
// Kernel 1b: qt[b,i] = scale * sum_h Q[b,h] * Wk[h,i]   (identical to R15)
// ---------------------------------------------------------------------------
__global__ __launch_bounds__(256) void qt_kernel(
    const float* __restrict__ Wk)    // [256, 512]
{
    const int b    = blockIdx.x >> 2;
    const int i0   = (blockIdx.x & 3) * 128;
    const int tid  = threadIdx.x;
    const int col  = i0 + (tid & 127);
    const int hh   = tid >> 7;          // 0 or 1

    __shared__ __align__(16) float sQ[HDIM_];
    __shared__ float s_part[256];
    sQ[tid] = g_Q[b * HDIM_ + tid];
    __syncthreads();

    float a[8];
    #pragma unroll
    for (int k = 0; k < 8; ++k) a[k] = 0.f;

    const int hbase = hh * 128;
    #pragma unroll 4
    for (int h = 0; h < 128; h += 8) {
        #pragma unroll
        for (int k = 0; k < 8; ++k)
            a[k] = fmaf(sQ[hbase + h + k],
                        Wk[(size_t)(hbase + h + k) * IDIM_ + col], a[k]);
    }
    s_part[tid] = ((a[0] + a[1]) + (a[2] + a[3])) + ((a[4] + a[5]) + (a[6] + a[7]));
    __syncthreads();

    if (tid < 128) {
        const float scale = 0.0625f;  // 1/sqrt(256)
        g_qt[b * IDIM_ + i0 + tid] = (s_part[tid] + s_part[tid + 128]) * scale;
    }
}

// ---------------------------------------------------------------------------
// Kernel 2: flash softmax-pooling, PER-WARP-PRIVATE state (identical to R15).
// ---------------------------------------------------------------------------
__global__ __launch_bounds__(256, 4) void flash_pool_kernel(
    const float* __restrict__ X,     // [64,16,256,512]
    const void*  __restrict__ mask)  // [64,16,256] u8 or i32
{
    const int bs   = blockIdx.x;
    const int b    = bs >> 4;
    const int tid  = threadIdx.x;
    const int wid  = tid >> 5;
    const int lane = tid & 31;

    __shared__ __align__(16) float4 s_stage[3][CHK_ * 128];  // 3 x 16 KB (also merge buf)
    __shared__ float s_m[8], s_d[8];

    const float4* x4 = reinterpret_cast<const float4*>(X + (size_t)bs * J_ * IDIM_);

    int mval;
    {
        const int j = lane * CHK_ + wid;   // 0..255
        if (g_mask_u8)
            mval = ((const uint8_t*)mask)[(size_t)bs * J_ + j];
        else
            mval = ((const int*)mask)[(size_t)bs * J_ + j];
    }

    float4 qv[4];
    {
        const float4* q4 = reinterpret_cast<const float4*>(g_qt + b * IDIM_);
        #pragma unroll
        for (int k = 0; k < 4; ++k) qv[k] = q4[lane + 32 * k];
    }

    const unsigned sbase = (unsigned)__cvta_generic_to_shared(&s_stage[0][0]);
    const unsigned BUFB  = (unsigned)(CHK_ * 128 * 16);

    #pragma unroll
    for (int u = 0; u < 4; ++u)
        cp_async16(sbase + (unsigned)(tid + 256 * u) * 16u, x4 + tid + 256 * u);
    cp_commit();
    #pragma unroll
    for (int u = 0; u < 4; ++u)
        cp_async16(sbase + BUFB + (unsigned)(tid + 256 * u) * 16u,
                   x4 + CHK_ * 128 + tid + 256 * u);
    cp_commit();

    float m = -1e30f, d = 0.f;
    float4 p[4];
    #pragma unroll
    for (int k = 0; k < 4; ++k) p[k] = make_float4(0.f, 0.f, 0.f, 0.f);

    int cur = 0, nxt2 = 2;

    for (int c = 0; c < NCHK_; ++c) {
        if (c == NCHK_ - 1) cp_wait0(); else cp_wait1();
        __syncthreads();

        if (c + 2 < NCHK_) {
            const unsigned sb = sbase + (unsigned)nxt2 * BUFB;
            const float4* src = x4 + (size_t)(c + 2) * (CHK_ * 128);
            #pragma unroll
            for (int u = 0; u < 4; ++u)
                cp_async16(sb + (unsigned)(tid + 256 * u) * 16u, src + tid + 256 * u);
            cp_commit();
        }

        const float4* r0 = &s_stage[cur][wid * 128];
        float4 xv[4];
        #pragma unroll
        for (int k = 0; k < 4; ++k) xv[k] = r0[lane + 32 * k];

        float s = 0.f;
        #pragma unroll
        for (int k = 0; k < 4; ++k) {
            s = fmaf(xv[k].x, qv[k].x, s);
            s = fmaf(xv[k].y, qv[k].y, s);
            s = fmaf(xv[k].z, qv[k].z, s);
            s = fmaf(xv[k].w, qv[k].w, s);
        }
        #pragma unroll
        for (int off = 16; off > 0; off >>= 1)
            s += __shfl_xor_sync(0xffffffffu, s, off);

        if (__shfl_sync(0xffffffffu, mval, c) != 0) s = -1e30f;

        const float mn = fmaxf(m, s);
        const float f  = __expf(m - mn);
        const float w  = __expf(s - mn);
        m = mn;
        d = fmaf(d, f, w);
        #pragma unroll
        for (int k = 0; k < 4; ++k) {
            p[k].x = fmaf(p[k].x, f, w * xv[k].x);
            p[k].y = fmaf(p[k].y, f, w * xv[k].y);
            p[k].z = fmaf(p[k].z, f, w * xv[k].z);
            p[k].w = fmaf(p[k].w, f, w * xv[k].w);
        }

        cur  = (cur == 2)  ? 0 : cur + 1;
        nxt2 = (nxt2 == 2) ? 0 : nxt2 + 1;
    }

    __syncthreads();
    if (lane == 0) { s_m[wid] = m; s_d[wid] = d; }
    {
        float4* mp = reinterpret_cast<float4*>(&s_stage[0][0]);
        #pragma unroll
        for (int k = 0; k < 4; ++k) mp[wid * 128 + lane + 32 * k] = p[k];
    }
    __syncthreads();

    float M = -1e30f;
    #pragma unroll
    for (int w = 0; w < 8; ++w) M = fmaxf(M, s_m[w]);
    float coef[8];
    float D = 0.f;
    #pragma unroll
    for (int w = 0; w < 8; ++w) {
        coef[w] = __expf(s_m[w] - M);
        D = fmaf(s_d[w], coef[w], D);
    }
    const float inv = 1.f / D;

    const float2* mp2 = reinterpret_cast<const float2*>(&s_stage[0][0]);
    float ox = 0.f, oy = 0.f;
    #pragma unroll
    for (int w = 0; w < 8; ++w) {
        const float2 v = mp2[w * 256 + tid];
        ox = fmaf(v.x, coef[w], ox);
        oy = fmaf(v.y, coef[w], oy);
    }
    reinterpret_cast<float2*>(g_pooled + (size_t)bs * IDIM_)[tid] =
        make_float2(ox * inv, oy * inv);
}

// ---------------------------------------------------------------------------
// Kernel 3: split-K GEMM with FFMA2 (fma.rn.f32x2) + triple-buffered cp.async
// out[1024,256] = pooled[1024,512] @ WvT[512,256]
// BM=32, BN=64, BK=32; 512 threads = 2 k-halves x 256; grid 128.
// Triple buffers -> one named barrier per chunk; inner loop uses 64-bit FMA.
// ---------------------------------------------------------------------------
#define BM_ 32
#define BN_ 64
#define BK_ 32
#define SAP_ 36
__global__ __launch_bounds__(512) void epilogue_kernel(float* __restrict__ out)
{
    const int tid = threadIdx.x;
    const int kh  = tid >> 8;          // k-half: 0 or 1
    const int t   = tid & 255;
    const int h0  = blockIdx.x * BN_;
    const int m0  = blockIdx.y * BM_;
    const int tx  = t & 15;
    const int ty  = t >> 4;

    __shared__ __align__(16) float sA[2][3][BM_][SAP_];   // 2x3x4.5 KB = 27 KB
    __shared__ __align__(16) float sB[2][3][BK_][BN_];    // 2x3x8   KB = 48 KB
    __shared__ __align__(16) float sP[BM_][BN_];          // 8 KB

    // acc as f32x2 pairs: acc2[row][pair] covers cols {4tx..4tx+3}
    unsigned long long acc2[2][2] = {{0ull, 0ull}, {0ull, 0ull}};

    const int ar = t >> 3;            // 0..31 (m row)
    const int ac = (t & 7) * 4;       // k col (float4)
    const int br = t >> 4;            // 0..15 (k row)
    const int bc = (t & 15) * 4;      // n col (float4)
    const int kbase = kh * 256;       // this half's k-range start

    const unsigned sAu = (unsigned)__cvta_generic_to_shared(&sA[kh][0][0][0]);
    const unsigned sBu = (unsigned)__cvta_generic_to_shared(&sB[kh][0][0][0]);
    const unsigned ABUF = (unsigned)(BM_ * SAP_ * 4);
    const unsigned BBUF = (unsigned)(BK_ * BN_ * 4);

    // Issue chunks 0 and 1 of this half into buffers 0 and 1
    #pragma unroll
    for (int pre = 0; pre < 2; ++pre) {
        const int k0 = kbase + pre * BK_;
        const unsigned oa = sAu + (unsigned)pre * ABUF;
        const unsigned ob = sBu + (unsigned)pre * BBUF;
        cp_async16(oa + (unsigned)(ar * SAP_ + ac) * 4u,
                   g_pooled + (size_t)(m0 + ar) * IDIM_ + k0 + ac);
        #pragma unroll
        for (int r = 0; r < 2; ++r) {
            const int kk = br + 16 * r;
            cp_async16(ob + (unsigned)(kk * BN_ + bc) * 4u,
                       g_WvT + (size_t)(k0 + kk) * HDIM_ + h0 + bc);
        }
        cp_commit();
    }

    const int NCH = 256 / BK_;   // 8 chunks per half
    int cur = 0, nxt2 = 2;

    for (int c = 0; c < NCH; ++c) {
        if (c == NCH - 1) cp_wait0(); else cp_wait1();   // chunk c landed
        asm volatile("bar.sync %0, 256;" :: "r"(kh + 1) : "memory");

        if (c + 2 < NCH) {
            const int k0 = kbase + (c + 2) * BK_;
            const unsigned oa = sAu + (unsigned)nxt2 * ABUF;
            const unsigned ob = sBu + (unsigned)nxt2 * BBUF;
            cp_async16(oa + (unsigned)(ar * SAP_ + ac) * 4u,
                       g_pooled + (size_t)(m0 + ar) * IDIM_ + k0 + ac);
            #pragma unroll
            for (int r = 0; r < 2; ++r) {
                const int kk = br + 16 * r;
                cp_async16(ob + (unsigned)(kk * BN_ + bc) * 4u,
                           g_WvT + (size_t)(k0 + kk) * HDIM_ + h0 + bc);
            }
            cp_commit();
        }

        #pragma unroll
        for (int kk = 0; kk < BK_; ++kk) {
            const float a0 = sA[kh][cur][ty * 2 + 0][kk];
            const float a1 = sA[kh][cur][ty * 2 + 1][kk];
            const ulonglong2 bv = *reinterpret_cast<const ulonglong2*>(
                &sB[kh][cur][kk][tx * 4]);   // ld.shared.v2.u64 (16B aligned)
            const unsigned long long a0p = pack2(a0);
            const unsigned long long a1p = pack2(a1);
            acc2[0][0] = ffma2(a0p, bv.x, acc2[0][0]);
            acc2[0][1] = ffma2(a0p, bv.y, acc2[0][1]);
            acc2[1][0] = ffma2(a1p, bv.x, acc2[1][0]);
            acc2[1][1] = ffma2(a1p, bv.y, acc2[1][1]);
        }
        // no trailing barrier: triple buffer -> next issue targets a buffer
        // last consumed two chunks ago (ordered by this iteration's barrier)

        cur  = (cur == 2)  ? 0 : cur + 1;
        nxt2 = (nxt2 == 2) ? 0 : nxt2 + 1;
    }

    // Unpack accumulators
    float acc[2][4];
    #pragma unroll
    for (int i = 0; i < 2; ++i) {
        unpack2(acc[i][0], acc[i][1], acc2[i][0]);
        unpack2(acc[i][2], acc[i][3], acc2[i][1]);
    }

    // Combine halves: half 1 stashes, half 0 adds and stores
    if (kh == 1) {
        #pragma unroll
        for (int i = 0; i < 2; ++i)
            *reinterpret_cast<float4*>(&sP[ty * 2 + i][tx * 4]) =
                make_float4(acc[i][0], acc[i][1], acc[i][2], acc[i][3]);
    }
    __syncthreads();
    if (kh == 0) {
        #pragma unroll
        for (int i = 0; i < 2; ++i) {
            const float4 o = *reinterpret_cast<const float4*>(&sP[ty * 2 + i][tx * 4]);
            const float4 v = make_float4(acc[i][0] + o.x, acc[i][1] + o.y,
                                         acc[i][2] + o.z, acc[i][3] + o.w);
            *reinterpret_cast<float4*>(
                out + (size_t)(m0 + ty * 2 + i) * HDIM_ + h0 + tx * 4) = v;
        }
    }
}

// ---------------------------------------------------------------------------
// Launch.  Inputs: query, other_semesters, mask, Wq, Wk, Wv
// ---------------------------------------------------------------------------
extern "C" void kernel_launch(void* const* d_in, const int* in_sizes, int n_in,
                              void* d_out, int out_size)
{
    const float* query = (const float*)d_in[0];
    const float* X     = (const float*)d_in[1];
    const void*  mask  = d_in[2];
    const float* Wq    = (const float*)d_in[3];
    const float* Wk    = (const float*)d_in[4];
    const float* Wv    = (const float*)d_in[5];
    float*       out   = (float*)d_out;

    prologue_kernel<<<192, 256>>>(query, Wq, Wv, (const unsigned*)mask);
    qt_kernel<<<256, 256>>>(Wk);
    flash_pool_kernel<<<BS_, 256>>>(X, mask);
    epilogue_kernel<<<dim3(HDIM_ / BN_, BS_ / BM_), 512>>>(out);
}

// round 17
// speedup vs baseline: 1.0319x; 1.0150x over previous
#include <cuda_runtime.h>
#include <cstdint>

// Shapes (fixed)
#define B_    64
#define S_    16
#define J_    256
#define QDIM_ 512
#define IDIM_ 512
#define HDIM_ 256
#define BS_   (B_ * S_)    // 1024
#define CHK_  8            // rows per staged chunk
#define NCHK_ (J_ / CHK_)  // 32 chunks

// Scratch (__device__ globals; 16B-aligned: accessed as float4/float2)
__device__ __align__(16) float g_Q[B_ * HDIM_];        // Wq q               [64, 256]
__device__ __align__(16) float g_qt[B_ * IDIM_];       // scale*Wk^T(Wq q)   [64, 512]
__device__ __align__(16) float g_pooled[BS_ * IDIM_];  // pooled inputs      [1024, 512]
__device__ __align__(16) float g_WvT[IDIM_ * HDIM_];   // Wv^T               [512, 256]
__device__ int g_mask_u8;                              // 1 = u8 bool mask, 0 = int32

// ---------------- cp.async helpers ----------------
__device__ __forceinline__ void cp_async16(unsigned dst_smem, const void* src) {
    asm volatile("cp.async.cg.shared.global [%0], [%1], 16;"
                 :: "r"(dst_smem), "l"(src));
}
__device__ __forceinline__ void cp_commit() {
    asm volatile("cp.async.commit_group;");
}
__device__ __forceinline__ void cp_wait0() {
    asm volatile("cp.async.wait_group 0;");
}
__device__ __forceinline__ void cp_wait1() {
    asm volatile("cp.async.wait_group 1;");
}

// ---------------- f32x2 (FFMA2) helpers ----------------
__device__ __forceinline__ unsigned long long ffma2(
    unsigned long long a, unsigned long long b, unsigned long long c) {
    unsigned long long d;
    asm("fma.rn.f32x2 %0, %1, %2, %3;" : "=l"(d) : "l"(a), "l"(b), "l"(c));
    return d;
}
__device__ __forceinline__ unsigned long long pack2(float x) {
    unsigned long long d;
    asm("mov.b64 %0, {%1, %1};" : "=l"(d) : "f"(x));
    return d;
}
__device__ __forceinline__ void unpack2(float& lo, float& hi, unsigned long long v) {
    asm("mov.b64 {%0, %1}, %2;" : "=f"(lo), "=f"(hi) : "l"(v));
}

// ---------------------------------------------------------------------------
// Kernel 1 (prologue), grid = 192, block = 256:  (body identical to R16;
// + early PDL trigger so qt can launch during our drain)
// ---------------------------------------------------------------------------
__global__ __launch_bounds__(256) void prologue_kernel(
    const float*    __restrict__ query,  // [64, 512]
    const float*    __restrict__ Wq,     // [256, 512]
    const float*    __restrict__ Wv,     // [256, 512]
    const unsigned* __restrict__ mask_words)
{
    cudaTriggerProgrammaticLaunchCompletion();

    const int bx  = blockIdx.x;
    const int tid = threadIdx.x;

    if (bx < 128) {
        if (bx == 0) {   // mask dtype detection
            __shared__ int flag;
            if (tid == 0) flag = 0;
            __syncthreads();
            int loc = 0;
            #pragma unroll
            for (int k = 0; k < 4; ++k)
                if (mask_words[tid + 256 * k] > 1u) loc = 1;
            if (loc) flag = 1;
            __syncthreads();
            if (tid == 0) g_mask_u8 = flag;
        }
        __shared__ __align__(16) float tile[32][33];
        const int i0 = (bx & 15) * 32;
        const int h0 = (bx >> 4) * 32;
        const int tx = tid & 31;
        const int ty = tid >> 5;
        #pragma unroll
        for (int r = 0; r < 32; r += 8)
            tile[ty + r][tx] = Wv[(size_t)(h0 + ty + r) * IDIM_ + i0 + tx];
        __syncthreads();
        #pragma unroll
        for (int r = 0; r < 32; r += 8)
            g_WvT[(size_t)(i0 + ty + r) * HDIM_ + h0 + tx] = tile[tx][ty + r];
    } else {
        const int b    = bx - 128;
        const int wid  = tid >> 5;
        const int lane = tid & 31;

        __shared__ __align__(16) float sq[QDIM_];
        sq[tid]       = query[b * QDIM_ + tid];
        sq[tid + 256] = query[b * QDIM_ + tid + 256];
        __syncthreads();

        float4 qr[4];
        {
            const float4* q4 = reinterpret_cast<const float4*>(sq);
            #pragma unroll
            for (int k = 0; k < 4; ++k) qr[k] = q4[lane + 32 * k];
        }

        #pragma unroll 2
        for (int t = 0; t < 32; t += 2) {
            const int h = wid * 32 + t;
            const float4* w0 = reinterpret_cast<const float4*>(Wq + (size_t)h * QDIM_);
            const float4* w1 = reinterpret_cast<const float4*>(Wq + (size_t)(h + 1) * QDIM_);
            float s0 = 0.f, s1 = 0.f;
            #pragma unroll
            for (int k = 0; k < 4; ++k) {
                const float4 a = w0[lane + 32 * k];
                const float4 c = w1[lane + 32 * k];
                s0 = fmaf(a.x, qr[k].x, s0); s0 = fmaf(a.y, qr[k].y, s0);
                s0 = fmaf(a.z, qr[k].z, s0); s0 = fmaf(a.w, qr[k].w, s0);
                s1 = fmaf(c.x, qr[k].x, s1); s1 = fmaf(c.y, qr[k].y, s1);
                s1 = fmaf(c.z, qr[k].z, s1); s1 = fmaf(c.w, qr[k].w, s1);
            }
            #pragma unroll
            for (int off = 16; off > 0; off >>= 1) {
                s0 += __shfl_xor_sync(0xffffffffu, s0, off);
                s1 += __shfl_xor_sync(0xffffffffu, s1, off);
            }
            if (lane == 0) {
                g_Q[b * HDIM_ + h]     = s0;
                g_Q[b * HDIM_ + h + 1] = s1;
            }
        }
    }
}

// ---------------------------------------------------------------------------
// Kernel 1b: qt[b,i] = scale * sum_h Q[b,h] * Wk[h,i]
// PDL secondary: griddepsync before reading g_Q; trigger early for flash.
// ---------------------------------------------------------------------------
__global__ __launch_bounds__(256) void qt_kernel(
    const float* __restrict__ Wk)    // [256, 512]
{
    cudaTriggerProgrammaticLaunchCompletion();
    cudaGridDependencySynchronize();   // wait for prologue's g_Q

    const int b    = blockIdx.x >> 2;
    const int i0   = (blockIdx.x & 3) * 128;
    const int tid  = threadIdx.x;
    const int col  = i0 + (tid & 127);
    const int hh   = tid >> 7;          // 0 or 1

    __shared__ __align__(16) float sQ[HDIM_];
    __shared__ float s_part[256];
    sQ[tid] = g_Q[b * HDIM_ + tid];
    __syncthreads();

    float a[8];
    #pragma unroll
    for (int k = 0; k < 8; ++k) a[k] = 0.f;

    const int hbase = hh * 128;
    #pragma unroll 4
    for (int h = 0; h < 128; h += 8) {
        #pragma unroll
        for (int k = 0; k < 8; ++k)
            a[k] = fmaf(sQ[hbase + h + k],
                        Wk[(size_t)(hbase + h + k) * IDIM_ + col], a[k]);
    }
    s_part[tid] = ((a[0] + a[1]) + (a[2] + a[3])) + ((a[4] + a[5]) + (a[6] + a[7]));
    __syncthreads();

    if (tid < 128) {
        const float scale = 0.0625f;  // 1/sqrt(256)
        g_qt[b * IDIM_ + i0 + tid] = (s_part[tid] + s_part[tid + 128]) * scale;
    }
}

// ---------------------------------------------------------------------------
// Kernel 2: flash softmax-pooling (body = R16). PDL secondary: issue chunk
// 0/1 cp.asyncs on input X BEFORE griddepsync (fill overlaps qt), then sync,
// then read g_qt/g_mask_u8. Trigger after main loop so epilogue launches
// during our merge/store tail.
// ---------------------------------------------------------------------------
__global__ __launch_bounds__(256, 4) void flash_pool_kernel(
    const float* __restrict__ X,     // [64,16,256,512]
    const void*  __restrict__ mask)  // [64,16,256] u8 or i32
{
    const int bs   = blockIdx.x;
    const int b    = bs >> 4;
    const int tid  = threadIdx.x;
    const int wid  = tid >> 5;
    const int lane = tid & 31;

    __shared__ __align__(16) float4 s_stage[3][CHK_ * 128];  // 3 x 16 KB (also merge buf)
    __shared__ float s_m[8], s_d[8];

    const float4* x4 = reinterpret_cast<const float4*>(X + (size_t)bs * J_ * IDIM_);

    const unsigned sbase = (unsigned)__cvta_generic_to_shared(&s_stage[0][0]);
    const unsigned BUFB  = (unsigned)(CHK_ * 128 * 16);

    // --- pre-dependency work: X is a kernel input, safe before sync ---
    #pragma unroll
    for (int u = 0; u < 4; ++u)
        cp_async16(sbase + (unsigned)(tid + 256 * u) * 16u, x4 + tid + 256 * u);
    cp_commit();
    #pragma unroll
    for (int u = 0; u < 4; ++u)
        cp_async16(sbase + BUFB + (unsigned)(tid + 256 * u) * 16u,
                   x4 + CHK_ * 128 + tid + 256 * u);
    cp_commit();

    cudaGridDependencySynchronize();   // qt's g_qt + prologue's g_mask_u8 ready

    int mval;
    {
        const int j = lane * CHK_ + wid;   // 0..255
        if (g_mask_u8)
            mval = ((const uint8_t*)mask)[(size_t)bs * J_ + j];
        else
            mval = ((const int*)mask)[(size_t)bs * J_ + j];
    }

    float4 qv[4];
    {
        const float4* q4 = reinterpret_cast<const float4*>(g_qt + b * IDIM_);
        #pragma unroll
        for (int k = 0; k < 4; ++k) qv[k] = q4[lane + 32 * k];
    }

    float m = -1e30f, d = 0.f;
    float4 p[4];
    #pragma unroll
    for (int k = 0; k < 4; ++k) p[k] = make_float4(0.f, 0.f, 0.f, 0.f);

    int cur = 0, nxt2 = 2;

    for (int c = 0; c < NCHK_; ++c) {
        if (c == NCHK_ - 1) cp_wait0(); else cp_wait1();
        __syncthreads();

        if (c + 2 < NCHK_) {
            const unsigned sb = sbase + (unsigned)nxt2 * BUFB;
            const float4* src = x4 + (size_t)(c + 2) * (CHK_ * 128);
            #pragma unroll
            for (int u = 0; u < 4; ++u)
                cp_async16(sb + (unsigned)(tid + 256 * u) * 16u, src + tid + 256 * u);
            cp_commit();
        }

        const float4* r0 = &s_stage[cur][wid * 128];
        float4 xv[4];
        #pragma unroll
        for (int k = 0; k < 4; ++k) xv[k] = r0[lane + 32 * k];

        float s = 0.f;
        #pragma unroll
        for (int k = 0; k < 4; ++k) {
            s = fmaf(xv[k].x, qv[k].x, s);
            s = fmaf(xv[k].y, qv[k].y, s);
            s = fmaf(xv[k].z, qv[k].z, s);
            s = fmaf(xv[k].w, qv[k].w, s);
        }
        #pragma unroll
        for (int off = 16; off > 0; off >>= 1)
            s += __shfl_xor_sync(0xffffffffu, s, off);

        if (__shfl_sync(0xffffffffu, mval, c) != 0) s = -1e30f;

        const float mn = fmaxf(m, s);
        const float f  = __expf(m - mn);
        const float w  = __expf(s - mn);
        m = mn;
        d = fmaf(d, f, w);
        #pragma unroll
        for (int k = 0; k < 4; ++k) {
            p[k].x = fmaf(p[k].x, f, w * xv[k].x);
            p[k].y = fmaf(p[k].y, f, w * xv[k].y);
            p[k].z = fmaf(p[k].z, f, w * xv[k].z);
            p[k].w = fmaf(p[k].w, f, w * xv[k].w);
        }

        cur  = (cur == 2)  ? 0 : cur + 1;
        nxt2 = (nxt2 == 2) ? 0 : nxt2 + 1;
    }

    cudaTriggerProgrammaticLaunchCompletion();   // epilogue may start launching

    __syncthreads();
    if (lane == 0) { s_m[wid] = m; s_d[wid] = d; }
    {
        float4* mp = reinterpret_cast<float4*>(&s_stage[0][0]);
        #pragma unroll
        for (int k = 0; k < 4; ++k) mp[wid * 128 + lane + 32 * k] = p[k];
    }
    __syncthreads();

    float M = -1e30f;
    #pragma unroll
    for (int w = 0; w < 8; ++w) M = fmaxf(M, s_m[w]);
    float coef[8];
    float D = 0.f;
    #pragma unroll
    for (int w = 0; w < 8; ++w) {
        coef[w] = __expf(s_m[w] - M);
        D = fmaf(s_d[w], coef[w], D);
    }
    const float inv = 1.f / D;

    const float2* mp2 = reinterpret_cast<const float2*>(&s_stage[0][0]);
    float ox = 0.f, oy = 0.f;
    #pragma unroll
    for (int w = 0; w < 8; ++w) {
        const float2 v = mp2[w * 256 + tid];
        ox = fmaf(v.x, coef[w], ox);
        oy = fmaf(v.y, coef[w], oy);
    }
    reinterpret_cast<float2*>(g_pooled + (size_t)bs * IDIM_)[tid] =
        make_float2(ox * inv, oy * inv);
}

// ---------------------------------------------------------------------------
// Kernel 3: split-K FFMA2 GEMM (body = R16). PDL secondary: prefetch B tiles
// (g_WvT — written by prologue, 3 kernels back, guaranteed complete) BEFORE
// griddepsync; then sync; then A tiles from g_pooled.
// Group layout: G0 = {B0,B1,A0}, G1 = {A1}, then one group per chunk.
// ---------------------------------------------------------------------------
#define BM_ 32
#define BN_ 64
#define BK_ 32
#define SAP_ 36
__global__ __launch_bounds__(512) void epilogue_kernel(float* __restrict__ out)
{
    const int tid = threadIdx.x;
    const int kh  = tid >> 8;          // k-half: 0 or 1
    const int t   = tid & 255;
    const int h0  = blockIdx.x * BN_;
    const int m0  = blockIdx.y * BM_;
    const int tx  = t & 15;
    const int ty  = t >> 4;

    __shared__ __align__(16) float sA[2][3][BM_][SAP_];   // 27 KB
    __shared__ __align__(16) float sB[2][3][BK_][BN_];    // 48 KB
    __shared__ __align__(16) float sP[BM_][BN_];          // 8 KB

    unsigned long long acc2[2][2] = {{0ull, 0ull}, {0ull, 0ull}};

    const int ar = t >> 3;            // 0..31 (m row)
    const int ac = (t & 7) * 4;       // k col (float4)
    const int br = t >> 4;            // 0..15 (k row)
    const int bc = (t & 15) * 4;      // n col (float4)
    const int kbase = kh * 256;

    const unsigned sAu = (unsigned)__cvta_generic_to_shared(&sA[kh][0][0][0]);
    const unsigned sBu = (unsigned)__cvta_generic_to_shared(&sB[kh][0][0][0]);
    const unsigned ABUF = (unsigned)(BM_ * SAP_ * 4);
    const unsigned BBUF = (unsigned)(BK_ * BN_ * 4);

    // --- pre-dependency: B tiles for buffers 0 and 1 (g_WvT is safe) ---
    #pragma unroll
    for (int pre = 0; pre < 2; ++pre) {
        const int k0 = kbase + pre * BK_;
        const unsigned ob = sBu + (unsigned)pre * BBUF;
        #pragma unroll
        for (int r = 0; r < 2; ++r) {
            const int kk = br + 16 * r;
            cp_async16(ob + (unsigned)(kk * BN_ + bc) * 4u,
                       g_WvT + (size_t)(k0 + kk) * HDIM_ + h0 + bc);
        }
    }

    cudaGridDependencySynchronize();   // flash's g_pooled ready

    // A tile buf0 -> commit (G0 = B0+B1+A0); A tile buf1 -> commit (G1 = A1)
    cp_async16(sAu + (unsigned)(ar * SAP_ + ac) * 4u,
               g_pooled + (size_t)(m0 + ar) * IDIM_ + kbase + ac);
    cp_commit();
    cp_async16(sAu + ABUF + (unsigned)(ar * SAP_ + ac) * 4u,
               g_pooled + (size_t)(m0 + ar) * IDIM_ + kbase + BK_ + ac);
    cp_commit();

    const int NCH = 256 / BK_;   // 8 chunks per half
    int cur = 0, nxt2 = 2;

    for (int c = 0; c < NCH; ++c) {
        if (c == NCH - 1) cp_wait0(); else cp_wait1();   // chunk c landed
        asm volatile("bar.sync %0, 256;" :: "r"(kh + 1) : "memory");

        if (c + 2 < NCH) {
            const int k0 = kbase + (c + 2) * BK_;
            const unsigned oa = sAu + (unsigned)nxt2 * ABUF;
            const unsigned ob = sBu + (unsigned)nxt2 * BBUF;
            cp_async16(oa + (unsigned)(ar * SAP_ + ac) * 4u,
                       g_pooled + (size_t)(m0 + ar) * IDIM_ + k0 + ac);
            #pragma unroll
            for (int r = 0; r < 2; ++r) {
                const int kk = br + 16 * r;
                cp_async16(ob + (unsigned)(kk * BN_ + bc) * 4u,
                           g_WvT + (size_t)(k0 + kk) * HDIM_ + h0 + bc);
            }
            cp_commit();
        }

        #pragma unroll
        for (int kk = 0; kk < BK_; ++kk) {
            const float a0 = sA[kh][cur][ty * 2 + 0][kk];
            const float a1 = sA[kh][cur][ty * 2 + 1][kk];
            const ulonglong2 bv = *reinterpret_cast<const ulonglong2*>(
                &sB[kh][cur][kk][tx * 4]);
            const unsigned long long a0p = pack2(a0);
            const unsigned long long a1p = pack2(a1);
            acc2[0][0] = ffma2(a0p, bv.x, acc2[0][0]);
            acc2[0][1] = ffma2(a0p, bv.y, acc2[0][1]);
            acc2[1][0] = ffma2(a1p, bv.x, acc2[1][0]);
            acc2[1][1] = ffma2(a1p, bv.y, acc2[1][1]);
        }

        cur  = (cur == 2)  ? 0 : cur + 1;
        nxt2 = (nxt2 == 2) ? 0 : nxt2 + 1;
    }

    float acc[2][4];
    #pragma unroll
    for (int i = 0; i < 2; ++i) {
        unpack2(acc[i][0], acc[i][1], acc2[i][0]);
        unpack2(acc[i][2], acc[i][3], acc2[i][1]);
    }

    if (kh == 1) {
        #pragma unroll
        for (int i = 0; i < 2; ++i)
            *reinterpret_cast<float4*>(&sP[ty * 2 + i][tx * 4]) =
                make_float4(acc[i][0], acc[i][1], acc[i][2], acc[i][3]);
    }
    __syncthreads();
    if (kh == 0) {
        #pragma unroll
        for (int i = 0; i < 2; ++i) {
            const float4 o = *reinterpret_cast<const float4*>(&sP[ty * 2 + i][tx * 4]);
            const float4 v = make_float4(acc[i][0] + o.x, acc[i][1] + o.y,
                                         acc[i][2] + o.z, acc[i][3] + o.w);
            *reinterpret_cast<float4*>(
                out + (size_t)(m0 + ty * 2 + i) * HDIM_ + h0 + tx * 4) = v;
        }
    }
}

// ---------------------------------------------------------------------------
// Launch.  Inputs: query, other_semesters, mask, Wq, Wk, Wv
// qt/flash/epilogue launch with Programmatic Stream Serialization (PDL).
// ---------------------------------------------------------------------------
static void launch_pdl(void* func, dim3 grid, dim3 block, void** args)
{
    cudaLaunchConfig_t cfg = {};
    cfg.gridDim  = grid;
    cfg.blockDim = block;
    cfg.stream   = 0;
    cudaLaunchAttribute attr[1];
    attr[0].id = cudaLaunchAttributeProgrammaticStreamSerialization;
    attr[0].val.programmaticStreamSerializationAllowed = 1;
    cfg.attrs = attr;
    cfg.numAttrs = 1;
    cudaLaunchKernelExC(&cfg, func, args);
}

extern "C" void kernel_launch(void* const* d_in, const int* in_sizes, int n_in,
                              void* d_out, int out_size)
{
    const float* query = (const float*)d_in[0];
    const float* X     = (const float*)d_in[1];
    const void*  mask  = d_in[2];
    const float* Wq    = (const float*)d_in[3];
    const float* Wk    = (const float*)d_in[4];
    const float* Wv    = (const float*)d_in[5];
    float*       out   = (float*)d_out;

    prologue_kernel<<<192, 256>>>(query, Wq, Wv, (const unsigned*)mask);

    {   // qt (PDL over prologue)
        void* args[] = { (void*)&Wk };
        launch_pdl((void*)qt_kernel, dim3(256), dim3(256), args);
    }
    {   // flash (PDL over qt)
        void* args[] = { (void*)&X, (void*)&mask };
        launch_pdl((void*)flash_pool_kernel, dim3(BS_), dim3(256), args);
    }
    {   // epilogue (PDL over flash)
        void* args[] = { (void*)&out };
        launch_pdl((void*)epilogue_kernel,
                   dim3(HDIM_ / BN_, BS_ / BM_), dim3(512), args);
    }
}